// round 16
// baseline (speedup 1.0000x reference)
#include <cuda_runtime.h>
#include <cuda_fp16.h>
#include <cstdint>
#include <math.h>

#define Hdim   1024
#define RANKK  4
#define BATCHN 128
#define TSTEPS 256
#define MTOT   (BATCHN * TSTEPS)      // 32768

// ======================= helpers =======================
__device__ __forceinline__ uint32_t smem_u32(const void* p) {
    uint32_t a;
    asm("{ .reg .u64 t; cvta.to.shared.u64 t, %1; cvt.u32.u64 %0, t; }" : "=r"(a) : "l"(p));
    return a;
}
__device__ __forceinline__ void cp16(uint32_t dst, const void* src) {
    asm volatile("cp.async.cg.shared.global [%0], [%1], 16;" :: "r"(dst), "l"(src) : "memory");
}
#define CP_COMMIT() asm volatile("cp.async.commit_group;" ::: "memory")

__device__ __forceinline__ void ldsm4(uint32_t* r, uint32_t addr) {
    asm volatile("ldmatrix.sync.aligned.m8n8.x4.shared.b16 {%0,%1,%2,%3}, [%4];"
        : "=r"(r[0]), "=r"(r[1]), "=r"(r[2]), "=r"(r[3]) : "r"(addr));
}
__device__ __forceinline__ void ldsm4t(uint32_t* r, uint32_t addr) {
    asm volatile("ldmatrix.sync.aligned.m8n8.x4.trans.shared.b16 {%0,%1,%2,%3}, [%4];"
        : "=r"(r[0]), "=r"(r[1]), "=r"(r[2]), "=r"(r[3]) : "r"(addr));
}
__device__ __forceinline__ void mma16816(float* c, const uint32_t* a, uint32_t b0, uint32_t b1) {
    asm volatile("mma.sync.aligned.m16n8k16.row.col.f32.f16.f16.f32 "
        "{%0,%1,%2,%3}, {%4,%5,%6,%7}, {%8,%9}, {%0,%1,%2,%3};"
        : "+f"(c[0]), "+f"(c[1]), "+f"(c[2]), "+f"(c[3])
        : "r"(a[0]), "r"(a[1]), "r"(a[2]), "r"(a[3]), "r"(b0), "r"(b1));
}

// ======================= fp16 scratch =======================
__device__ __align__(256) __half g_xf[(size_t)MTOT * Hdim];   // 64 MB
__device__ __align__(256) __half g_Bf[(size_t)Hdim * Hdim];   // 2 MB  [k][n]

#define NX4 ((size_t)MTOT * Hdim / 4)
#define NB4 ((size_t)Hdim * Hdim / 4)

__global__ __launch_bounds__(256) void conv_all_kernel(const float* __restrict__ x,
                                                       const float* __restrict__ B) {
    size_t i = (size_t)blockIdx.x * 256 + threadIdx.x;
    const float4* src;
    __half* dst;
    size_t j;
    if (i < NX4) { src = (const float4*)x; dst = g_xf; j = i; }
    else if (i < NX4 + NB4) { src = (const float4*)B; dst = g_Bf; j = i - NX4; }
    else return;
    float4 v = src[j];
    union { __half h[4]; uint2 u; } o;
    o.h[0] = __float2half_rn(v.x);
    o.h[1] = __float2half_rn(v.y);
    o.h[2] = __float2half_rn(v.z);
    o.h[3] = __float2half_rn(v.w);
    *(uint2*)&dst[4 * j] = o.u;
}

// ======================= HMMA GEMM (proven: fp16, 3-stage, 2 CTA/SM) =======================
#define BK     32
#define NCHNK  32
#define ASTRIDE 40                   // halves per A smem row (80 B)
#define BSTRIDE 136                  // halves per B smem row (272 B)
#define ASTG   (128 * ASTRIDE * 2)   // 10240 B
#define BSTG   (BK * BSTRIDE * 2)    // 8704 B
#define NSTAGE 3
#define SMEM_GEMM (NSTAGE * (ASTG + BSTG))   // 56832 B

__device__ __forceinline__ void load_chunk_g(uint32_t sA, uint32_t sB,
                                             int m0, int n0, int k0, int tid) {
    const int arow = tid >> 2, aseg = tid & 3;
    const int brow = tid >> 4, bseg = tid & 15;
    #pragma unroll
    for (int i = 0; i < 2; i++) {
        int ra = arow + i * 64;
        cp16(sA + ra * 80 + aseg * 16, g_xf + (size_t)(m0 + ra) * Hdim + k0 + aseg * 8);
        int rb = brow + i * 16;
        cp16(sB + rb * 272 + bseg * 16, g_Bf + (size_t)(k0 + rb) * Hdim + n0 + bseg * 8);
    }
}

__global__ __launch_bounds__(256, 2) void gemm_mma(float* __restrict__ C) {
    extern __shared__ char smem[];
    const uint32_t sb  = smem_u32(smem);
    const uint32_t sbB = sb + NSTAGE * ASTG;
    const int tid = threadIdx.x, lane = tid & 31, wid = tid >> 5;
    const int wm = (wid >> 1) * 32;
    const int wn = (wid & 1) * 64;
    const int n0 = blockIdx.x * 128;
    const int m0 = blockIdx.y * 128;

    const int r8 = lane & 7, g = lane >> 3;
    const int mrow = (g & 1) * 8 + r8;
    const int kcolB = (g >> 1) * 16;
    uint32_t offA0 = (uint32_t)(wm + mrow) * 80 + kcolB;
    uint32_t offA1 = (uint32_t)(wm + 16 + mrow) * 80 + kcolB;
    uint32_t offB[4];
    #pragma unroll
    for (int ng = 0; ng < 4; ng++)
        offB[ng] = (uint32_t)mrow * 272 + (uint32_t)(wn + ng * 16) * 2 + kcolB;

    float acc[2][8][4] = {};

    load_chunk_g(sb, sbB, m0, n0, 0, tid);  CP_COMMIT();
    load_chunk_g(sb + ASTG, sbB + BSTG, m0, n0, 32, tid);  CP_COMMIT();

    for (int c = 0; c < NCHNK; c++) {
        const int s = c % NSTAGE;
        asm volatile("cp.async.wait_group 1;" ::: "memory");
        __syncthreads();

        if (c + 2 < NCHNK) {
            const int cn = c + 2, sn = cn % NSTAGE;
            load_chunk_g(sb + sn * ASTG, sbB + sn * BSTG, m0, n0, cn * BK, tid);
        }
        CP_COMMIT();

        const uint32_t aB = sb + s * ASTG;
        const uint32_t bB = sbB + s * BSTG;
        #pragma unroll
        for (int ks = 0; ks < 2; ks++) {
            uint32_t a[2][4];
            ldsm4(a[0], aB + offA0 + ks * 32);
            ldsm4(a[1], aB + offA1 + ks * 32);
            uint32_t b[4][4];
            #pragma unroll
            for (int ng = 0; ng < 4; ng++)
                ldsm4t(b[ng], bB + offB[ng] + ks * 16 * 272);
            #pragma unroll
            for (int mt = 0; mt < 2; mt++)
                #pragma unroll
                for (int nt = 0; nt < 8; nt++)
                    mma16816(acc[mt][nt], a[mt], b[nt >> 1][(nt & 1) * 2], b[nt >> 1][(nt & 1) * 2 + 1]);
        }
    }

    #pragma unroll
    for (int mt = 0; mt < 2; mt++) {
        const int row = m0 + wm + mt * 16 + (lane >> 2);
        #pragma unroll
        for (int nt = 0; nt < 8; nt++) {
            const int col = n0 + wn + nt * 8 + (lane & 3) * 2;
            *(float2*)&C[(size_t)row * Hdim + col]       = make_float2(acc[mt][nt][0], acc[mt][nt][1]);
            *(float2*)&C[(size_t)(row + 8) * Hdim + col] = make_float2(acc[mt][nt][2], acc[mt][nt][3]);
        }
    }
}

// ======================= recurrence (R6 shape, HW tanh) =======================
__device__ __forceinline__ float tanh_hw(float x) {
    float r;
    asm("tanh.approx.f32 %0, %1;" : "=f"(r) : "f"(x));
    return r;
}

__global__ __launch_bounds__(256) void recur(const float* __restrict__ h0,
                                             const float* __restrict__ dvec,
                                             const float* __restrict__ L,
                                             const float* __restrict__ R,
                                             float* __restrict__ out) {
    const int b = blockIdx.x, tid = threadIdx.x;
    const int warp = tid >> 5, lane = tid & 31, h = tid * 4;
    __shared__ float4 part[2][8];

    float4 hs = *(const float4*)(h0 + (size_t)b * Hdim + h);
    float4 dr = *(const float4*)(dvec + h);
    float4 L0 = *(const float4*)(L + (size_t)(h + 0) * RANKK);
    float4 L1 = *(const float4*)(L + (size_t)(h + 1) * RANKK);
    float4 L2 = *(const float4*)(L + (size_t)(h + 2) * RANKK);
    float4 L3 = *(const float4*)(L + (size_t)(h + 3) * RANKK);
    float4 R0 = *(const float4*)(R + 0 * Hdim + h);
    float4 R1 = *(const float4*)(R + 1 * Hdim + h);
    float4 R2 = *(const float4*)(R + 2 * Hdim + h);
    float4 R3 = *(const float4*)(R + 3 * Hdim + h);

    float* row = out + (size_t)b * TSTEPS * Hdim;
    float4 u = *(const float4*)(row + h);
    for (int t = 0; t < TSTEPS; t++) {
        float4 u_next = make_float4(0.f, 0.f, 0.f, 0.f);
        if (t + 1 < TSTEPS) u_next = *(const float4*)(row + (size_t)(t + 1) * Hdim + h);

        float p0 = R0.x * hs.x + R0.y * hs.y + R0.z * hs.z + R0.w * hs.w;
        float p1 = R1.x * hs.x + R1.y * hs.y + R1.z * hs.z + R1.w * hs.w;
        float p2 = R2.x * hs.x + R2.y * hs.y + R2.z * hs.z + R2.w * hs.w;
        float p3 = R3.x * hs.x + R3.y * hs.y + R3.z * hs.z + R3.w * hs.w;
        #pragma unroll
        for (int off = 16; off >= 1; off >>= 1) {
            p0 += __shfl_xor_sync(0xFFFFFFFFu, p0, off);
            p1 += __shfl_xor_sync(0xFFFFFFFFu, p1, off);
            p2 += __shfl_xor_sync(0xFFFFFFFFu, p2, off);
            p3 += __shfl_xor_sync(0xFFFFFFFFu, p3, off);
        }
        if (lane == 0) part[t & 1][warp] = make_float4(p0, p1, p2, p3);
        __syncthreads();

        float v0 = 0.f, v1 = 0.f, v2 = 0.f, v3 = 0.f;
        #pragma unroll
        for (int w = 0; w < 8; w++) {
            float4 pw = part[t & 1][w];
            v0 += pw.x; v1 += pw.y; v2 += pw.z; v3 += pw.w;
        }
        float a0 = fmaf(dr.x, hs.x, u.x);
        float a1 = fmaf(dr.y, hs.y, u.y);
        float a2 = fmaf(dr.z, hs.z, u.z);
        float a3 = fmaf(dr.w, hs.w, u.w);
        a0 = fmaf(L0.x, v0, fmaf(L0.y, v1, fmaf(L0.z, v2, fmaf(L0.w, v3, a0))));
        a1 = fmaf(L1.x, v0, fmaf(L1.y, v1, fmaf(L1.z, v2, fmaf(L1.w, v3, a1))));
        a2 = fmaf(L2.x, v0, fmaf(L2.y, v1, fmaf(L2.z, v2, fmaf(L2.w, v3, a2))));
        a3 = fmaf(L3.x, v0, fmaf(L3.y, v1, fmaf(L3.z, v2, fmaf(L3.w, v3, a3))));
        hs.x = tanh_hw(a0); hs.y = tanh_hw(a1); hs.z = tanh_hw(a2); hs.w = tanh_hw(a3);
        *(float4*)(row + (size_t)t * Hdim + h) = hs;
        u = u_next;
    }
}

// ======================= launch =======================
extern "C" void kernel_launch(void* const* d_in, const int* in_sizes, int n_in,
                              void* d_out, int out_size) {
    const float* x  = (const float*)d_in[0];
    const float* h0 = (const float*)d_in[1];
    const float* d  = (const float*)d_in[2];
    const float* L  = (const float*)d_in[3];
    const float* R  = (const float*)d_in[4];
    const float* B  = (const float*)d_in[5];
    float* out = (float*)d_out;

    cudaFuncSetAttribute(gemm_mma, cudaFuncAttributeMaxDynamicSharedMemorySize, SMEM_GEMM);

    size_t total4 = NX4 + NB4;
    conv_all_kernel<<<(unsigned)((total4 + 255) / 256), 256>>>(x, B);
    gemm_mma<<<dim3(Hdim / 128, MTOT / 128), 256, SMEM_GEMM>>>(out);
    recur<<<BATCHN, 256>>>(h0, d, L, R, out);
}

// round 17
// speedup vs baseline: 1.0743x; 1.0743x over previous
#include <cuda_runtime.h>
#include <cuda_fp16.h>
#include <cstdint>
#include <math.h>

#define Hdim   1024
#define RANKK  4
#define BATCHN 128
#define TSTEPS 256
#define MTOT   (BATCHN * TSTEPS)      // 32768

// ======================= helpers =======================
__device__ __forceinline__ uint32_t smem_u32(const void* p) {
    uint32_t a;
    asm("{ .reg .u64 t; cvta.to.shared.u64 t, %1; cvt.u32.u64 %0, t; }" : "=r"(a) : "l"(p));
    return a;
}
__device__ __forceinline__ void cp16(uint32_t dst, const void* src) {
    asm volatile("cp.async.cg.shared.global [%0], [%1], 16;" :: "r"(dst), "l"(src) : "memory");
}
#define CP_COMMIT() asm volatile("cp.async.commit_group;" ::: "memory")

__device__ __forceinline__ void ldsm4(uint32_t* r, uint32_t addr) {
    asm volatile("ldmatrix.sync.aligned.m8n8.x4.shared.b16 {%0,%1,%2,%3}, [%4];"
        : "=r"(r[0]), "=r"(r[1]), "=r"(r[2]), "=r"(r[3]) : "r"(addr));
}
__device__ __forceinline__ void ldsm4t(uint32_t* r, uint32_t addr) {
    asm volatile("ldmatrix.sync.aligned.m8n8.x4.trans.shared.b16 {%0,%1,%2,%3}, [%4];"
        : "=r"(r[0]), "=r"(r[1]), "=r"(r[2]), "=r"(r[3]) : "r"(addr));
}
__device__ __forceinline__ void mma16816(float* c, const uint32_t* a, uint32_t b0, uint32_t b1) {
    asm volatile("mma.sync.aligned.m16n8k16.row.col.f32.f16.f16.f32 "
        "{%0,%1,%2,%3}, {%4,%5,%6,%7}, {%8,%9}, {%0,%1,%2,%3};"
        : "+f"(c[0]), "+f"(c[1]), "+f"(c[2]), "+f"(c[3])
        : "r"(a[0]), "r"(a[1]), "r"(a[2]), "r"(a[3]), "r"(b0), "r"(b1));
}

// ======================= fp16 scratch =======================
__device__ __align__(256) __half g_xf[(size_t)MTOT * Hdim];   // 64 MB
__device__ __align__(256) __half g_Bf[(size_t)Hdim * Hdim];   // 2 MB  [k][n]

#define NX4 ((size_t)MTOT * Hdim / 4)
#define NB4 ((size_t)Hdim * Hdim / 4)

__global__ __launch_bounds__(256) void conv_all_kernel(const float* __restrict__ x,
                                                       const float* __restrict__ B) {
    size_t i = (size_t)blockIdx.x * 256 + threadIdx.x;
    const float4* src;
    __half* dst;
    size_t j;
    if (i < NX4) { src = (const float4*)x; dst = g_xf; j = i; }
    else if (i < NX4 + NB4) { src = (const float4*)B; dst = g_Bf; j = i - NX4; }
    else return;
    float4 v = src[j];
    union { __half h[4]; uint2 u; } o;
    o.h[0] = __float2half_rn(v.x);
    o.h[1] = __float2half_rn(v.y);
    o.h[2] = __float2half_rn(v.z);
    o.h[3] = __float2half_rn(v.w);
    *(uint2*)&dst[4 * j] = o.u;
}

// ======================= HMMA GEMM (proven: fp16, 3-stage, 2 CTA/SM) =======================
#define BK     32
#define NCHNK  32
#define ASTRIDE 40
#define BSTRIDE 136
#define ASTG   (128 * ASTRIDE * 2)   // 10240 B
#define BSTG   (BK * BSTRIDE * 2)    // 8704 B
#define NSTAGE 3
#define SMEM_GEMM (NSTAGE * (ASTG + BSTG))   // 56832 B

__device__ __forceinline__ void load_chunk_g(uint32_t sA, uint32_t sB,
                                             int m0, int n0, int k0, int tid) {
    const int arow = tid >> 2, aseg = tid & 3;
    const int brow = tid >> 4, bseg = tid & 15;
    #pragma unroll
    for (int i = 0; i < 2; i++) {
        int ra = arow + i * 64;
        cp16(sA + ra * 80 + aseg * 16, g_xf + (size_t)(m0 + ra) * Hdim + k0 + aseg * 8);
        int rb = brow + i * 16;
        cp16(sB + rb * 272 + bseg * 16, g_Bf + (size_t)(k0 + rb) * Hdim + n0 + bseg * 8);
    }
}

__global__ __launch_bounds__(256, 2) void gemm_mma(float* __restrict__ C) {
    extern __shared__ char smem[];
    const uint32_t sb  = smem_u32(smem);
    const uint32_t sbB = sb + NSTAGE * ASTG;
    const int tid = threadIdx.x, lane = tid & 31, wid = tid >> 5;
    const int wm = (wid >> 1) * 32;
    const int wn = (wid & 1) * 64;
    const int n0 = blockIdx.x * 128;
    const int m0 = blockIdx.y * 128;

    const int r8 = lane & 7, g = lane >> 3;
    const int mrow = (g & 1) * 8 + r8;
    const int kcolB = (g >> 1) * 16;
    uint32_t offA0 = (uint32_t)(wm + mrow) * 80 + kcolB;
    uint32_t offA1 = (uint32_t)(wm + 16 + mrow) * 80 + kcolB;
    uint32_t offB[4];
    #pragma unroll
    for (int ng = 0; ng < 4; ng++)
        offB[ng] = (uint32_t)mrow * 272 + (uint32_t)(wn + ng * 16) * 2 + kcolB;

    float acc[2][8][4] = {};

    load_chunk_g(sb, sbB, m0, n0, 0, tid);  CP_COMMIT();
    load_chunk_g(sb + ASTG, sbB + BSTG, m0, n0, 32, tid);  CP_COMMIT();

    for (int c = 0; c < NCHNK; c++) {
        const int s = c % NSTAGE;
        asm volatile("cp.async.wait_group 1;" ::: "memory");
        __syncthreads();

        if (c + 2 < NCHNK) {
            const int cn = c + 2, sn = cn % NSTAGE;
            load_chunk_g(sb + sn * ASTG, sbB + sn * BSTG, m0, n0, cn * BK, tid);
        }
        CP_COMMIT();

        const uint32_t aB = sb + s * ASTG;
        const uint32_t bB = sbB + s * BSTG;
        #pragma unroll
        for (int ks = 0; ks < 2; ks++) {
            uint32_t a[2][4];
            ldsm4(a[0], aB + offA0 + ks * 32);
            ldsm4(a[1], aB + offA1 + ks * 32);
            uint32_t b[4][4];
            #pragma unroll
            for (int ng = 0; ng < 4; ng++)
                ldsm4t(b[ng], bB + offB[ng] + ks * 16 * 272);
            #pragma unroll
            for (int mt = 0; mt < 2; mt++)
                #pragma unroll
                for (int nt = 0; nt < 8; nt++)
                    mma16816(acc[mt][nt], a[mt], b[nt >> 1][(nt & 1) * 2], b[nt >> 1][(nt & 1) * 2 + 1]);
        }
    }

    #pragma unroll
    for (int mt = 0; mt < 2; mt++) {
        const int row = m0 + wm + mt * 16 + (lane >> 2);
        #pragma unroll
        for (int nt = 0; nt < 8; nt++) {
            const int col = n0 + wn + nt * 8 + (lane & 3) * 2;
            *(float2*)&C[(size_t)row * Hdim + col]       = make_float2(acc[mt][nt][0], acc[mt][nt][1]);
            *(float2*)&C[(size_t)(row + 8) * Hdim + col] = make_float2(acc[mt][nt][2], acc[mt][nt][3]);
        }
    }
}

// ======================= recurrence: lane-parallel reduction tail =======================
__device__ __forceinline__ float tanh_hw(float x) {
    float r;
    asm("tanh.approx.f32 %0, %1;" : "=f"(r) : "f"(x));
    return r;
}

__global__ __launch_bounds__(256) void recur(const float* __restrict__ h0,
                                             const float* __restrict__ dvec,
                                             const float* __restrict__ L,
                                             const float* __restrict__ R,
                                             float* __restrict__ out) {
    const int b = blockIdx.x, tid = threadIdx.x;
    const int warp = tid >> 5, lane = tid & 31, h = tid * 4;
    __shared__ float part[2][32];   // [parity][warp*4 + rank]

    float4 hs = *(const float4*)(h0 + (size_t)b * Hdim + h);
    float4 dr = *(const float4*)(dvec + h);
    float4 L0 = *(const float4*)(L + (size_t)(h + 0) * RANKK);
    float4 L1 = *(const float4*)(L + (size_t)(h + 1) * RANKK);
    float4 L2 = *(const float4*)(L + (size_t)(h + 2) * RANKK);
    float4 L3 = *(const float4*)(L + (size_t)(h + 3) * RANKK);
    float4 R0 = *(const float4*)(R + 0 * Hdim + h);
    float4 R1 = *(const float4*)(R + 1 * Hdim + h);
    float4 R2 = *(const float4*)(R + 2 * Hdim + h);
    float4 R3 = *(const float4*)(R + 3 * Hdim + h);

    float* row = out + (size_t)b * TSTEPS * Hdim;
    float4 u = *(const float4*)(row + h);
    for (int t = 0; t < TSTEPS; t++) {
        float4 u_next = make_float4(0.f, 0.f, 0.f, 0.f);
        if (t + 1 < TSTEPS) u_next = *(const float4*)(row + (size_t)(t + 1) * Hdim + h);

        // per-warp rank partials over this warp's 128 h-values
        float p0 = R0.x * hs.x + R0.y * hs.y + R0.z * hs.z + R0.w * hs.w;
        float p1 = R1.x * hs.x + R1.y * hs.y + R1.z * hs.z + R1.w * hs.w;
        float p2 = R2.x * hs.x + R2.y * hs.y + R2.z * hs.z + R2.w * hs.w;
        float p3 = R3.x * hs.x + R3.y * hs.y + R3.z * hs.z + R3.w * hs.w;
        #pragma unroll
        for (int off = 16; off >= 1; off >>= 1) {
            p0 += __shfl_xor_sync(0xFFFFFFFFu, p0, off);
            p1 += __shfl_xor_sync(0xFFFFFFFFu, p1, off);
            p2 += __shfl_xor_sync(0xFFFFFFFFu, p2, off);
            p3 += __shfl_xor_sync(0xFFFFFFFFu, p3, off);
        }
        if (lane == 0) *(float4*)&part[t & 1][warp * 4] = make_float4(p0, p1, p2, p3);
        __syncthreads();

        // lane-parallel tail: flat[32] = 8 warps x 4 ranks.
        // lane l loads flat[l] (partial of warp l>>2, rank l&3);
        // xor-sum over warps (offsets 4,8,16) -> lane holds v_{l&3};
        // shfl.idx gathers v0..v3 to every lane.
        float s = part[t & 1][lane];
        s += __shfl_xor_sync(0xFFFFFFFFu, s, 4);
        s += __shfl_xor_sync(0xFFFFFFFFu, s, 8);
        s += __shfl_xor_sync(0xFFFFFFFFu, s, 16);
        const int base = lane & 28;   // (lane & ~3)
        float v0 = __shfl_sync(0xFFFFFFFFu, s, base + 0);
        float v1 = __shfl_sync(0xFFFFFFFFu, s, base + 1);
        float v2 = __shfl_sync(0xFFFFFFFFu, s, base + 2);
        float v3 = __shfl_sync(0xFFFFFFFFu, s, base + 3);

        float a0 = fmaf(dr.x, hs.x, u.x);
        float a1 = fmaf(dr.y, hs.y, u.y);
        float a2 = fmaf(dr.z, hs.z, u.z);
        float a3 = fmaf(dr.w, hs.w, u.w);
        a0 = fmaf(L0.x, v0, fmaf(L0.y, v1, fmaf(L0.z, v2, fmaf(L0.w, v3, a0))));
        a1 = fmaf(L1.x, v0, fmaf(L1.y, v1, fmaf(L1.z, v2, fmaf(L1.w, v3, a1))));
        a2 = fmaf(L2.x, v0, fmaf(L2.y, v1, fmaf(L2.z, v2, fmaf(L2.w, v3, a2))));
        a3 = fmaf(L3.x, v0, fmaf(L3.y, v1, fmaf(L3.z, v2, fmaf(L3.w, v3, a3))));
        hs.x = tanh_hw(a0); hs.y = tanh_hw(a1); hs.z = tanh_hw(a2); hs.w = tanh_hw(a3);
        *(float4*)(row + (size_t)t * Hdim + h) = hs;
        u = u_next;
    }
}

// ======================= launch =======================
extern "C" void kernel_launch(void* const* d_in, const int* in_sizes, int n_in,
                              void* d_out, int out_size) {
    const float* x  = (const float*)d_in[0];
    const float* h0 = (const float*)d_in[1];
    const float* d  = (const float*)d_in[2];
    const float* L  = (const float*)d_in[3];
    const float* R  = (const float*)d_in[4];
    const float* B  = (const float*)d_in[5];
    float* out = (float*)d_out;

    cudaFuncSetAttribute(gemm_mma, cudaFuncAttributeMaxDynamicSharedMemorySize, SMEM_GEMM);

    size_t total4 = NX4 + NB4;
    conv_all_kernel<<<(unsigned)((total4 + 255) / 256), 256>>>(x, B);
    gemm_mma<<<dim3(Hdim / 128, MTOT / 128), 256, SMEM_GEMM>>>(out);
    recur<<<BATCHN, 256>>>(h0, d, L, R, out);
}